// round 1
// baseline (speedup 1.0000x reference)
#include <cuda_runtime.h>
#include <math_constants.h>

#define BB 32
#define HH 32
#define KVH 8
#define G 4            // HH / KVH
#define HD 128
#define BS 16
#define MAX_KV 4096
#define BPS 256        // blocks per seq
#define CHUNK 256
#define SPLITS (MAX_KV / CHUNK)   // 16
#define NWARP 8
#define NEG_BIG (-1.0e30f)

__device__ float  g_pout[BB * KVH * SPLITS * G * HD];   // unnormalized partial outputs
__device__ float2 g_pml [BB * KVH * SPLITS * G];        // (m, l) per split per head

__device__ __forceinline__ void online_update(float x, float4 v,
                                              float& m, float& l, float4& a) {
    if (x > m) {
        float f = __expf(m - x);
        m = x;
        l *= f;
        a.x *= f; a.y *= f; a.z *= f; a.w *= f;
    }
    float p = __expf(x - m);
    l += p;
    a.x += p * v.x; a.y += p * v.y; a.z += p * v.z; a.w += p * v.w;
}

__global__ __launch_bounds__(256, 3)
void attn_split_kernel(const float* __restrict__ q,
                       const float* __restrict__ kc,
                       const float* __restrict__ vc,
                       const int*   __restrict__ seqlens,
                       const int*   __restrict__ btab)
{
    const int split = blockIdx.x;
    const int kh    = blockIdx.y;
    const int b     = blockIdx.z;
    const float scale = 0.08838834764831845f; // 1/sqrt(128)

    const int sl = seqlens[b];
    const int cs = split * CHUNK;
    const int pml_base = ((b * KVH + kh) * SPLITS + split) * G;

    if (cs >= sl) {
        if (threadIdx.x < G)
            g_pml[pml_base + threadIdx.x] = make_float2(NEG_BIG, 0.0f);
        return;
    }
    const int ce = min(cs + CHUNK, sl);

    const int tid  = threadIdx.x;
    const int w    = tid >> 5;
    const int lane = tid & 31;

    // Load the 4 query heads for this kv head: each lane holds float4 of each head.
    const float4* qp = (const float4*)(q + (size_t)(b * HH + kh * G) * HD);
    const float4 q0 = qp[0 * 32 + lane];
    const float4 q1 = qp[1 * 32 + lane];
    const float4 q2 = qp[2 * 32 + lane];
    const float4 q3 = qp[3 * 32 + lane];

    const int* tb = btab + b * BPS;

    float m0 = NEG_BIG, m1 = NEG_BIG, m2 = NEG_BIG, m3 = NEG_BIG;
    float l0 = 0.f, l1 = 0.f, l2 = 0.f, l3 = 0.f;
    float4 a0 = make_float4(0, 0, 0, 0), a1 = a0, a2 = a0, a3 = a0;

    int t = cs + w;
    float4 k4 = make_float4(0, 0, 0, 0), v4 = k4;
    if (t < ce) {
        int bid = __ldg(tb + (t >> 4));
        int off = ((bid * BS + (t & 15)) * KVH + kh) * HD;
        k4 = ((const float4*)(kc + off))[lane];
        v4 = ((const float4*)(vc + off))[lane];
    }

    while (t < ce) {
        float4 ck = k4, cv = v4;
        int tn = t + NWARP;
        if (tn < ce) {
            int bid = __ldg(tb + (tn >> 4));
            int off = ((bid * BS + (tn & 15)) * KVH + kh) * HD;
            k4 = ((const float4*)(kc + off))[lane];
            v4 = ((const float4*)(vc + off))[lane];
        }

        float s0 = ck.x * q0.x + ck.y * q0.y + ck.z * q0.z + ck.w * q0.w;
        float s1 = ck.x * q1.x + ck.y * q1.y + ck.z * q1.z + ck.w * q1.w;
        float s2 = ck.x * q2.x + ck.y * q2.y + ck.z * q2.z + ck.w * q2.w;
        float s3 = ck.x * q3.x + ck.y * q3.y + ck.z * q3.z + ck.w * q3.w;

        #pragma unroll
        for (int o = 16; o; o >>= 1) {
            s0 += __shfl_xor_sync(0xffffffffu, s0, o);
            s1 += __shfl_xor_sync(0xffffffffu, s1, o);
            s2 += __shfl_xor_sync(0xffffffffu, s2, o);
            s3 += __shfl_xor_sync(0xffffffffu, s3, o);
        }

        online_update(s0 * scale, cv, m0, l0, a0);
        online_update(s1 * scale, cv, m1, l1, a1);
        online_update(s2 * scale, cv, m2, l2, a2);
        online_update(s3 * scale, cv, m3, l3, a3);

        t = tn;
    }

    // ---- combine the 8 warps via shared memory ----
    __shared__ float smAcc[NWARP][G][HD];
    __shared__ float smM[NWARP][G];
    __shared__ float smL[NWARP][G];

    ((float4*)&smAcc[w][0][0])[lane] = a0;
    ((float4*)&smAcc[w][1][0])[lane] = a1;
    ((float4*)&smAcc[w][2][0])[lane] = a2;
    ((float4*)&smAcc[w][3][0])[lane] = a3;
    if (lane == 0) {
        smM[w][0] = m0; smM[w][1] = m1; smM[w][2] = m2; smM[w][3] = m3;
        smL[w][0] = l0; smL[w][1] = l1; smL[w][2] = l2; smL[w][3] = l3;
    }
    __syncthreads();

    for (int idx = tid; idx < G * HD; idx += 256) {
        int h = idx >> 7;
        int d = idx & 127;
        float M = NEG_BIG;
        #pragma unroll
        for (int ww = 0; ww < NWARP; ww++) M = fmaxf(M, smM[ww][h]);
        float L = 0.f, O = 0.f;
        #pragma unroll
        for (int ww = 0; ww < NWARP; ww++) {
            float e = __expf(smM[ww][h] - M);
            L += smL[ww][h] * e;
            O += smAcc[ww][h][d] * e;
        }
        g_pout[(pml_base + h) * HD + d] = O;
        if (d == 0) g_pml[pml_base + h] = make_float2(M, L);
    }
}

__global__ __launch_bounds__(128)
void attn_reduce_kernel(float* __restrict__ out)
{
    const int kh = blockIdx.x;
    const int b  = blockIdx.y;
    const int d  = threadIdx.x;

    #pragma unroll
    for (int h = 0; h < G; h++) {
        const int base = ((b * KVH + kh) * SPLITS) * G + h;   // + s*G strides splits
        float M = NEG_BIG;
        #pragma unroll 4
        for (int s = 0; s < SPLITS; s++) {
            float2 ml = g_pml[base + s * G];
            if (ml.y > 0.f) M = fmaxf(M, ml.x);
        }
        float L = 0.f, O = 0.f;
        #pragma unroll 4
        for (int s = 0; s < SPLITS; s++) {
            float2 ml = g_pml[base + s * G];
            if (ml.y > 0.f) {
                float e = __expf(ml.x - M);
                L += ml.y * e;
                O += g_pout[(base + s * G) * HD + d] * e;
            }
        }
        out[((size_t)(b * HH) + kh * G + h) * HD + d] = O / L;
    }
}

extern "C" void kernel_launch(void* const* d_in, const int* in_sizes, int n_in,
                              void* d_out, int out_size) {
    const float* q   = (const float*)d_in[0];
    const float* kc  = (const float*)d_in[1];
    const float* vc  = (const float*)d_in[2];
    const int*   sl  = (const int*)d_in[3];
    const int*   bt  = (const int*)d_in[4];
    float* out = (float*)d_out;

    dim3 g1(SPLITS, KVH, BB);
    attn_split_kernel<<<g1, 256>>>(q, kc, vc, sl, bt);
    dim3 g2(KVH, BB);
    attn_reduce_kernel<<<g2, 128>>>(out);
}

// round 2
// speedup vs baseline: 1.0030x; 1.0030x over previous
#include <cuda_runtime.h>

#define BB 32
#define HH 32
#define KVH 8
#define G 4            // HH / KVH
#define HD 128
#define BS 16
#define MAX_KV 4096
#define BPS 256        // blocks per seq
#define CHUNK 128
#define SPLITS (MAX_KV / CHUNK)   // 32
#define NWARP 8
#define NEG_BIG (-1.0e30f)

__device__ float  g_pout[BB * KVH * SPLITS * G * HD];   // unnormalized partial outputs
__device__ float2 g_pml [BB * KVH * SPLITS * G];        // (m, l) per split per head

__device__ __forceinline__ void ldkv(const float* __restrict__ kc,
                                     const float* __restrict__ vc,
                                     const int* __restrict__ tb,
                                     int kh, int t, int sub,
                                     float4& k0, float4& k1,
                                     float4& v0, float4& v1) {
    int bid = __ldg(tb + (t >> 4));
    size_t off = ((size_t)(bid * BS + (t & 15)) * KVH + kh) * HD;
    const float4* kp = (const float4*)(kc + off);
    const float4* vp = (const float4*)(vc + off);
    k0 = kp[sub * 2];
    k1 = kp[sub * 2 + 1];
    v0 = vp[sub * 2];
    v1 = vp[sub * 2 + 1];
}

__device__ __forceinline__ float dot8(float4 a0, float4 a1, float4 b0, float4 b1) {
    return a0.x * b0.x + a0.y * b0.y + a0.z * b0.z + a0.w * b0.w +
           a1.x * b1.x + a1.y * b1.y + a1.z * b1.z + a1.w * b1.w;
}

__global__ __launch_bounds__(256, 2)
void attn_split_kernel(const float* __restrict__ q,
                       const float* __restrict__ kc,
                       const float* __restrict__ vc,
                       const int*   __restrict__ seqlens,
                       const int*   __restrict__ btab)
{
    const int split = blockIdx.x;
    const int kh    = blockIdx.y;
    const int b     = blockIdx.z;
    const float scale = 0.08838834764831845f; // 1/sqrt(128)

    const int sl = seqlens[b];
    const int cs = split * CHUNK;
    const int pml_base = ((b * KVH + kh) * SPLITS + split) * G;

    if (cs >= sl) return;   // inactive split: reduce kernel caps by seqlen

    const int ce = min(cs + CHUNK, sl);

    const int tid  = threadIdx.x;
    const int w    = tid >> 5;
    const int lane = tid & 31;
    const int half = lane >> 4;
    const int sub  = lane & 15;

    // Q: each lane holds dims [sub*8, sub*8+8) of each of the 4 heads
    const float4* qp = (const float4*)(q + (size_t)(b * HH + kh * G) * HD);
    float4 q00 = qp[0 * 32 + sub * 2], q01 = qp[0 * 32 + sub * 2 + 1];
    float4 q10 = qp[1 * 32 + sub * 2], q11 = qp[1 * 32 + sub * 2 + 1];
    float4 q20 = qp[2 * 32 + sub * 2], q21 = qp[2 * 32 + sub * 2 + 1];
    float4 q30 = qp[3 * 32 + sub * 2], q31 = qp[3 * 32 + sub * 2 + 1];

    const int* tb = btab + b * BPS;

    float m0 = NEG_BIG, m1 = NEG_BIG, m2 = NEG_BIG, m3 = NEG_BIG;
    float l0 = 0.f, l1 = 0.f, l2 = 0.f, l3 = 0.f;
    float4 z = make_float4(0, 0, 0, 0);
    float4 a00 = z, a01 = z, a10 = z, a11 = z, a20 = z, a21 = z, a30 = z, a31 = z;

    // token for this half-warp this iteration; pair base advances by 16 (8 warps * 2)
    int t = cs + w * 2 + half;
    bool vld = t < ce;
    float4 kn0 = z, kn1 = z, vn0 = z, vn1 = z;
    if (vld) ldkv(kc, vc, tb, kh, t, sub, kn0, kn1, vn0, vn1);

    for (int tA = cs + w * 2; tA < ce; tA += 16) {
        float4 ck0 = kn0, ck1 = kn1, cv0 = vn0, cv1 = vn1;
        bool cvld = vld;
        int tn = t + 16;
        vld = tn < ce;
        if (vld) ldkv(kc, vc, tb, kh, tn, sub, kn0, kn1, vn0, vn1);
        t = tn;

        float s0 = dot8(ck0, ck1, q00, q01);
        float s1 = dot8(ck0, ck1, q10, q11);
        float s2 = dot8(ck0, ck1, q20, q21);
        float s3 = dot8(ck0, ck1, q30, q31);

        #pragma unroll
        for (int o = 8; o; o >>= 1) {
            s0 += __shfl_xor_sync(0xffffffffu, s0, o);
            s1 += __shfl_xor_sync(0xffffffffu, s1, o);
            s2 += __shfl_xor_sync(0xffffffffu, s2, o);
            s3 += __shfl_xor_sync(0xffffffffu, s3, o);
        }

        if (cvld) {
            // head 0
            {
                float x = s0 * scale;
                if (x > m0) { float f = __expf(m0 - x); m0 = x; l0 *= f;
                    a00.x *= f; a00.y *= f; a00.z *= f; a00.w *= f;
                    a01.x *= f; a01.y *= f; a01.z *= f; a01.w *= f; }
                float p = __expf(x - m0); l0 += p;
                a00.x += p * cv0.x; a00.y += p * cv0.y; a00.z += p * cv0.z; a00.w += p * cv0.w;
                a01.x += p * cv1.x; a01.y += p * cv1.y; a01.z += p * cv1.z; a01.w += p * cv1.w;
            }
            {
                float x = s1 * scale;
                if (x > m1) { float f = __expf(m1 - x); m1 = x; l1 *= f;
                    a10.x *= f; a10.y *= f; a10.z *= f; a10.w *= f;
                    a11.x *= f; a11.y *= f; a11.z *= f; a11.w *= f; }
                float p = __expf(x - m1); l1 += p;
                a10.x += p * cv0.x; a10.y += p * cv0.y; a10.z += p * cv0.z; a10.w += p * cv0.w;
                a11.x += p * cv1.x; a11.y += p * cv1.y; a11.z += p * cv1.z; a11.w += p * cv1.w;
            }
            {
                float x = s2 * scale;
                if (x > m2) { float f = __expf(m2 - x); m2 = x; l2 *= f;
                    a20.x *= f; a20.y *= f; a20.z *= f; a20.w *= f;
                    a21.x *= f; a21.y *= f; a21.z *= f; a21.w *= f; }
                float p = __expf(x - m2); l2 += p;
                a20.x += p * cv0.x; a20.y += p * cv0.y; a20.z += p * cv0.z; a20.w += p * cv0.w;
                a21.x += p * cv1.x; a21.y += p * cv1.y; a21.z += p * cv1.z; a21.w += p * cv1.w;
            }
            {
                float x = s3 * scale;
                if (x > m3) { float f = __expf(m3 - x); m3 = x; l3 *= f;
                    a30.x *= f; a30.y *= f; a30.z *= f; a30.w *= f;
                    a31.x *= f; a31.y *= f; a31.z *= f; a31.w *= f; }
                float p = __expf(x - m3); l3 += p;
                a30.x += p * cv0.x; a30.y += p * cv0.y; a30.z += p * cv0.z; a30.w += p * cv0.w;
                a31.x += p * cv1.x; a31.y += p * cv1.y; a31.z += p * cv1.z; a31.w += p * cv1.w;
            }
        }
    }

    // ---- merge the two 16-lane halves of each warp via shuffles ----
    #define MERGE_HALF(m, l, A0, A1)                                          \
    {                                                                         \
        float mo = __shfl_xor_sync(0xffffffffu, m, 16);                       \
        float Mn = fmaxf(m, mo);                                              \
        float f  = __expf(m - Mn);                                            \
        l *= f;                                                               \
        A0.x *= f; A0.y *= f; A0.z *= f; A0.w *= f;                           \
        A1.x *= f; A1.y *= f; A1.z *= f; A1.w *= f;                           \
        l += __shfl_xor_sync(0xffffffffu, l, 16);                             \
        A0.x += __shfl_xor_sync(0xffffffffu, A0.x, 16);                       \
        A0.y += __shfl_xor_sync(0xffffffffu, A0.y, 16);                       \
        A0.z += __shfl_xor_sync(0xffffffffu, A0.z, 16);                       \
        A0.w += __shfl_xor_sync(0xffffffffu, A0.w, 16);                       \
        A1.x += __shfl_xor_sync(0xffffffffu, A1.x, 16);                       \
        A1.y += __shfl_xor_sync(0xffffffffu, A1.y, 16);                       \
        A1.z += __shfl_xor_sync(0xffffffffu, A1.z, 16);                       \
        A1.w += __shfl_xor_sync(0xffffffffu, A1.w, 16);                       \
        m = Mn;                                                               \
    }
    MERGE_HALF(m0, l0, a00, a01)
    MERGE_HALF(m1, l1, a10, a11)
    MERGE_HALF(m2, l2, a20, a21)
    MERGE_HALF(m3, l3, a30, a31)
    #undef MERGE_HALF

    // ---- combine the 8 warps via shared memory ----
    __shared__ float smAcc[NWARP][G][HD];
    __shared__ float smM[NWARP][G];
    __shared__ float smL[NWARP][G];

    if (half == 0) {
        float4* p0 = (float4*)&smAcc[w][0][sub * 8];
        p0[0] = a00; p0[1] = a01;
        float4* p1 = (float4*)&smAcc[w][1][sub * 8];
        p1[0] = a10; p1[1] = a11;
        float4* p2 = (float4*)&smAcc[w][2][sub * 8];
        p2[0] = a20; p2[1] = a21;
        float4* p3 = (float4*)&smAcc[w][3][sub * 8];
        p3[0] = a30; p3[1] = a31;
        if (sub == 0) {
            smM[w][0] = m0; smM[w][1] = m1; smM[w][2] = m2; smM[w][3] = m3;
            smL[w][0] = l0; smL[w][1] = l1; smL[w][2] = l2; smL[w][3] = l3;
        }
    }
    __syncthreads();

    for (int idx = tid; idx < G * HD; idx += 256) {
        int h = idx >> 7;
        int d = idx & 127;
        float M = NEG_BIG;
        #pragma unroll
        for (int ww = 0; ww < NWARP; ww++) M = fmaxf(M, smM[ww][h]);
        float L = 0.f, O = 0.f;
        #pragma unroll
        for (int ww = 0; ww < NWARP; ww++) {
            float e = __expf(smM[ww][h] - M);
            L += smL[ww][h] * e;
            O += smAcc[ww][h][d] * e;
        }
        g_pout[(pml_base + h) * HD + d] = O;
        if (d == 0) g_pml[pml_base + h] = make_float2(M, L);
    }
}

__global__ __launch_bounds__(128)
void attn_reduce_kernel(const int* __restrict__ seqlens, float* __restrict__ out)
{
    const int bh = blockIdx.x;        // b * HH + h_glob
    const int b  = bh >> 5;
    const int hg = bh & 31;
    const int kh = hg >> 2;
    const int g  = hg & 3;
    const int d  = threadIdx.x;

    const int sl = seqlens[b];
    const int ns = (sl + CHUNK - 1) / CHUNK;   // active splits

    const int base = ((b * KVH + kh) * SPLITS) * G + g;  // + s*G strides splits

    float M = NEG_BIG;
    #pragma unroll 4
    for (int s = 0; s < ns; s++) {
        float2 ml = g_pml[base + s * G];
        if (ml.y > 0.f) M = fmaxf(M, ml.x);
    }
    float L = 0.f, O = 0.f;
    #pragma unroll 4
    for (int s = 0; s < ns; s++) {
        float2 ml = g_pml[base + s * G];
        if (ml.y > 0.f) {
            float e = __expf(ml.x - M);
            L += ml.y * e;
            O += g_pout[(base + s * G) * HD + d] * e;
        }
    }
    out[((size_t)bh) * HD + d] = O / L;
}

extern "C" void kernel_launch(void* const* d_in, const int* in_sizes, int n_in,
                              void* d_out, int out_size) {
    const float* q   = (const float*)d_in[0];
    const float* kc  = (const float*)d_in[1];
    const float* vc  = (const float*)d_in[2];
    const int*   sl  = (const int*)d_in[3];
    const int*   bt  = (const int*)d_in[4];
    float* out = (float*)d_out;

    dim3 g1(SPLITS, KVH, BB);
    attn_split_kernel<<<g1, 256>>>(q, kc, vc, sl, bt);
    attn_reduce_kernel<<<BB * HH, 128>>>(sl, out);
}

// round 3
// speedup vs baseline: 1.0769x; 1.0737x over previous
#include <cuda_runtime.h>

#define BB 32
#define HH 32
#define KVH 8
#define G 4            // HH / KVH
#define HD 128
#define BS 16
#define MAX_KV 4096
#define BPS 256        // blocks per seq
#define CHUNK 128
#define SPLITS (MAX_KV / CHUNK)   // 32
#define NWARP 8
#define NEG_BIG (-1.0e30f)

__device__ float  g_pout[BB * KVH * SPLITS * G * HD];   // unnormalized partial outputs
__device__ float2 g_pml [BB * KVH * SPLITS * G];        // (m, l) per split per head

__device__ __forceinline__ float dot8(float4 a0, float4 a1, float4 b0, float4 b1) {
    return a0.x * b0.x + a0.y * b0.y + a0.z * b0.z + a0.w * b0.w +
           a1.x * b1.x + a1.y * b1.y + a1.z * b1.z + a1.w * b1.w;
}

__global__ __launch_bounds__(256, 3)
void attn_split_kernel(const float* __restrict__ q,
                       const float* __restrict__ kc,
                       const float* __restrict__ vc,
                       const int*   __restrict__ seqlens,
                       const int*   __restrict__ btab)
{
    const int split = blockIdx.x;
    const int kh    = blockIdx.y;
    const int b     = blockIdx.z;
    const float scale = 0.08838834764831845f; // 1/sqrt(128)

    const int sl = seqlens[b];
    const int cs = split * CHUNK;
    const int pml_base = ((b * KVH + kh) * SPLITS + split) * G;
    const int tid = threadIdx.x;

    if (cs >= sl) {
        if (tid < G) g_pml[pml_base + tid] = make_float2(NEG_BIG, 0.0f);
        return;
    }
    const int ce = min(cs + CHUNK, sl);

    const int w    = tid >> 5;
    const int lane = tid & 31;
    const int half = lane >> 4;
    const int sub  = lane & 15;

    __shared__ float sc[G][CHUNK];              // scores, then p = exp(s-m)
    __shared__ float smAcc[NWARP][G][HD];       // per-warp V accumulators
    __shared__ int   sblk[CHUNK / BS];          // block ids for this chunk

    // init score buffer (tail tokens must read as -inf) + cache block ids
    for (int i = tid; i < G * CHUNK; i += 256) ((float*)sc)[i] = NEG_BIG;
    if (tid < CHUNK / BS) sblk[tid] = btab[b * BPS + (cs >> 4) + tid];

    // Q regs, pre-scaled: lane holds dims [sub*8, sub*8+8) of 4 heads
    const float4* qp = (const float4*)(q + (size_t)(b * HH + kh * G) * HD);
    float4 q00 = qp[0 * 32 + sub * 2], q01 = qp[0 * 32 + sub * 2 + 1];
    float4 q10 = qp[1 * 32 + sub * 2], q11 = qp[1 * 32 + sub * 2 + 1];
    float4 q20 = qp[2 * 32 + sub * 2], q21 = qp[2 * 32 + sub * 2 + 1];
    float4 q30 = qp[3 * 32 + sub * 2], q31 = qp[3 * 32 + sub * 2 + 1];
    #define SCL(v) v.x*=scale; v.y*=scale; v.z*=scale; v.w*=scale;
    SCL(q00) SCL(q01) SCL(q10) SCL(q11) SCL(q20) SCL(q21) SCL(q30) SCL(q31)
    #undef SCL

    __syncthreads();

    // ================= Pass 1: K -> scores =================
    {
        const int tbase = cs + w * 2;        // warp's first token pair
        int tme = tbase + half;              // this half-warp's token
        float4 kA0, kA1, kB0, kB1;
        bool vA = tme < ce;
        if (vA) {
            int bid = sblk[(tme - cs) >> 4];
            const float4* kp = (const float4*)(kc + ((size_t)(bid * BS + (tme & 15)) * KVH + kh) * HD);
            kA0 = kp[sub * 2]; kA1 = kp[sub * 2 + 1];
        }
        bool vB = (tme + 16) < ce;
        if (vB) {
            int t2 = tme + 16;
            int bid = sblk[(t2 - cs) >> 4];
            const float4* kp = (const float4*)(kc + ((size_t)(bid * BS + (t2 & 15)) * KVH + kh) * HD);
            kB0 = kp[sub * 2]; kB1 = kp[sub * 2 + 1];
        }

        for (int tw = tbase; tw < ce; tw += 16) {
            float4 c0 = kA0, c1 = kA1;
            bool cv = vA;
            int tcur = tme;
            // rotate buffers, prefetch t+32
            kA0 = kB0; kA1 = kB1; vA = vB;
            int tn = tme + 32;
            vB = tn < ce;
            if (vB) {
                int bid = sblk[(tn - cs) >> 4];
                const float4* kp = (const float4*)(kc + ((size_t)(bid * BS + (tn & 15)) * KVH + kh) * HD);
                kB0 = kp[sub * 2]; kB1 = kp[sub * 2 + 1];
            }
            tme += 16;

            float s0 = dot8(c0, c1, q00, q01);
            float s1 = dot8(c0, c1, q10, q11);
            float s2 = dot8(c0, c1, q20, q21);
            float s3 = dot8(c0, c1, q30, q31);
            #pragma unroll
            for (int o = 8; o; o >>= 1) {
                s0 += __shfl_xor_sync(0xffffffffu, s0, o);
                s1 += __shfl_xor_sync(0xffffffffu, s1, o);
                s2 += __shfl_xor_sync(0xffffffffu, s2, o);
                s3 += __shfl_xor_sync(0xffffffffu, s3, o);
            }
            if (cv && sub == 0) {
                int tt = tcur - cs;
                sc[0][tt] = s0; sc[1][tt] = s1; sc[2][tt] = s2; sc[3][tt] = s3;
            }
        }
    }
    __syncthreads();

    // ================= chunk softmax (warps 0..3, one head each) =================
    if (w < G) {
        float x0 = sc[w][lane +  0], x1 = sc[w][lane + 32];
        float x2 = sc[w][lane + 64], x3 = sc[w][lane + 96];
        float mx = fmaxf(fmaxf(x0, x1), fmaxf(x2, x3));
        #pragma unroll
        for (int o = 16; o; o >>= 1) mx = fmaxf(mx, __shfl_xor_sync(0xffffffffu, mx, o));
        float p0 = __expf(x0 - mx), p1 = __expf(x1 - mx);
        float p2 = __expf(x2 - mx), p3 = __expf(x3 - mx);
        float ls = p0 + p1 + p2 + p3;
        #pragma unroll
        for (int o = 16; o; o >>= 1) ls += __shfl_xor_sync(0xffffffffu, ls, o);
        sc[w][lane +  0] = p0; sc[w][lane + 32] = p1;
        sc[w][lane + 64] = p2; sc[w][lane + 96] = p3;
        if (lane == 0) g_pml[pml_base + w] = make_float2(mx, ls);
    }
    __syncthreads();

    // ================= Pass 2: V accumulation =================
    {
        float4 z = make_float4(0, 0, 0, 0);
        float4 a00 = z, a01 = z, a10 = z, a11 = z, a20 = z, a21 = z, a30 = z, a31 = z;

        const int tbase = cs + w * 2;
        int tme = tbase + half;
        float4 vA0, vA1, vB0, vB1;
        bool vA = tme < ce;
        if (vA) {
            int bid = sblk[(tme - cs) >> 4];
            const float4* vp = (const float4*)(vc + ((size_t)(bid * BS + (tme & 15)) * KVH + kh) * HD);
            vA0 = vp[sub * 2]; vA1 = vp[sub * 2 + 1];
        }
        bool vB = (tme + 16) < ce;
        if (vB) {
            int t2 = tme + 16;
            int bid = sblk[(t2 - cs) >> 4];
            const float4* vp = (const float4*)(vc + ((size_t)(bid * BS + (t2 & 15)) * KVH + kh) * HD);
            vB0 = vp[sub * 2]; vB1 = vp[sub * 2 + 1];
        }

        for (int tw = tbase; tw < ce; tw += 16) {
            float4 c0 = vA0, c1 = vA1;
            bool cv = vA;
            int tcur = tme;
            vA0 = vB0; vA1 = vB1; vA = vB;
            int tn = tme + 32;
            vB = tn < ce;
            if (vB) {
                int bid = sblk[(tn - cs) >> 4];
                const float4* vp = (const float4*)(vc + ((size_t)(bid * BS + (tn & 15)) * KVH + kh) * HD);
                vB0 = vp[sub * 2]; vB1 = vp[sub * 2 + 1];
            }
            tme += 16;

            if (cv) {
                int tt = tcur - cs;
                float p0 = sc[0][tt], p1 = sc[1][tt], p2 = sc[2][tt], p3 = sc[3][tt];
                a00.x += p0 * c0.x; a00.y += p0 * c0.y; a00.z += p0 * c0.z; a00.w += p0 * c0.w;
                a01.x += p0 * c1.x; a01.y += p0 * c1.y; a01.z += p0 * c1.z; a01.w += p0 * c1.w;
                a10.x += p1 * c0.x; a10.y += p1 * c0.y; a10.z += p1 * c0.z; a10.w += p1 * c0.w;
                a11.x += p1 * c1.x; a11.y += p1 * c1.y; a11.z += p1 * c1.z; a11.w += p1 * c1.w;
                a20.x += p2 * c0.x; a20.y += p2 * c0.y; a20.z += p2 * c0.z; a20.w += p2 * c0.w;
                a21.x += p2 * c1.x; a21.y += p2 * c1.y; a21.z += p2 * c1.z; a21.w += p2 * c1.w;
                a30.x += p3 * c0.x; a30.y += p3 * c0.y; a30.z += p3 * c0.z; a30.w += p3 * c0.w;
                a31.x += p3 * c1.x; a31.y += p3 * c1.y; a31.z += p3 * c1.z; a31.w += p3 * c1.w;
            }
        }

        // merge the two 16-lane halves (plain sums)
        #define MRG(f) f += __shfl_xor_sync(0xffffffffu, f, 16);
        MRG(a00.x) MRG(a00.y) MRG(a00.z) MRG(a00.w)
        MRG(a01.x) MRG(a01.y) MRG(a01.z) MRG(a01.w)
        MRG(a10.x) MRG(a10.y) MRG(a10.z) MRG(a10.w)
        MRG(a11.x) MRG(a11.y) MRG(a11.z) MRG(a11.w)
        MRG(a20.x) MRG(a20.y) MRG(a20.z) MRG(a20.w)
        MRG(a21.x) MRG(a21.y) MRG(a21.z) MRG(a21.w)
        MRG(a30.x) MRG(a30.y) MRG(a30.z) MRG(a30.w)
        MRG(a31.x) MRG(a31.y) MRG(a31.z) MRG(a31.w)
        #undef MRG

        if (half == 0) {
            float4* p0 = (float4*)&smAcc[w][0][sub * 8]; p0[0] = a00; p0[1] = a01;
            float4* p1 = (float4*)&smAcc[w][1][sub * 8]; p1[0] = a10; p1[1] = a11;
            float4* p2 = (float4*)&smAcc[w][2][sub * 8]; p2[0] = a20; p2[1] = a21;
            float4* p3 = (float4*)&smAcc[w][3][sub * 8]; p3[0] = a30; p3[1] = a31;
        }
    }
    __syncthreads();

    // ================= combine 8 warps, write partial output =================
    for (int idx = tid; idx < G * HD; idx += 256) {
        int h = idx >> 7;
        int d = idx & 127;
        float O = 0.f;
        #pragma unroll
        for (int ww = 0; ww < NWARP; ww++) O += smAcc[ww][h][d];
        g_pout[(pml_base + h) * HD + d] = O;
    }
}

__global__ __launch_bounds__(128)
void attn_reduce_kernel(float* __restrict__ out)
{
    const int bh = blockIdx.x;        // b * HH + h_glob
    const int b  = bh >> 5;
    const int hg = bh & 31;
    const int kh = hg >> 2;
    const int g  = hg & 3;
    const int d  = threadIdx.x;

    const int base = ((b * KVH + kh) * SPLITS) * G + g;  // + s*G strides splits

    float2 ml[SPLITS];
    #pragma unroll
    for (int s = 0; s < SPLITS; s++) ml[s] = g_pml[base + s * G];

    float M = NEG_BIG;
    #pragma unroll
    for (int s = 0; s < SPLITS; s++) M = fmaxf(M, ml[s].x);

    float L = 0.f, O = 0.f;
    #pragma unroll
    for (int s = 0; s < SPLITS; s++) {
        float e = __expf(ml[s].x - M);     // inactive: exp(NEG_BIG - M) == 0
        L += ml[s].y * e;
        O += g_pout[(base + s * G) * HD + d] * e;
    }
    out[((size_t)bh) * HD + d] = O / L;
}

extern "C" void kernel_launch(void* const* d_in, const int* in_sizes, int n_in,
                              void* d_out, int out_size) {
    const float* q   = (const float*)d_in[0];
    const float* kc  = (const float*)d_in[1];
    const float* vc  = (const float*)d_in[2];
    const int*   sl  = (const int*)d_in[3];
    const int*   bt  = (const int*)d_in[4];
    float* out = (float*)d_out;

    dim3 g1(SPLITS, KVH, BB);
    attn_split_kernel<<<g1, 256>>>(q, kc, vc, sl, bt);
    attn_reduce_kernel<<<BB * HH, 128>>>(out);
}

// round 4
// speedup vs baseline: 1.1720x; 1.0883x over previous
#include <cuda_runtime.h>

#define BB 32
#define HH 32
#define KVH 8
#define G 4            // HH / KVH
#define HD 128
#define BS 16
#define MAX_KV 4096
#define BPS 256        // blocks per seq
#define CHUNK 128
#define SPLITS (MAX_KV / CHUNK)   // 32
#define NWARP 8
#define NITER 8        // pair-iterations per chunk: CHUNK / (NWARP*2)
#define NEG_BIG (-1.0e30f)

// g_pout layout: [b][kh][g][split][d]  (contiguous in split,d for the reducer)
__device__ float  g_pout[BB * KVH * G * SPLITS * HD];
__device__ float2 g_pml [BB * KVH * SPLITS * G];

__device__ __forceinline__ float dot8(float4 a0, float4 a1, float4 b0, float4 b1) {
    return a0.x * b0.x + a0.y * b0.y + a0.z * b0.z + a0.w * b0.w +
           a1.x * b1.x + a1.y * b1.y + a1.z * b1.z + a1.w * b1.w;
}

__global__ __launch_bounds__(256, 3)
void attn_split_kernel(const float* __restrict__ q,
                       const float* __restrict__ kc,
                       const float* __restrict__ vc,
                       const int*   __restrict__ seqlens,
                       const int*   __restrict__ btab)
{
    const int split = blockIdx.x;
    const int kh    = blockIdx.y;
    const int b     = blockIdx.z;
    const float scale = 0.08838834764831845f; // 1/sqrt(128)

    const int sl = seqlens[b];
    const int cs = split * CHUNK;
    const int pml_base = ((b * KVH + kh) * SPLITS + split) * G;
    const int tid = threadIdx.x;

    if (cs >= sl) return;                     // reducer caps by seqlen
    const int ce = min(cs + CHUNK, sl);

    const int w    = tid >> 5;
    const int lane = tid & 31;
    const int half = lane >> 4;
    const int sub  = lane & 15;

    __shared__ float sc[G][CHUNK];            // scores, then p = exp(s-m)
    __shared__ float smAcc[NWARP][G][HD];     // per-warp V accumulators
    __shared__ int   sblk[CHUNK / BS];        // block ids for this chunk

    for (int i = tid; i < G * CHUNK; i += 256) ((float*)sc)[i] = NEG_BIG;
    if (tid < CHUNK / BS) sblk[tid] = btab[b * BPS + (cs >> 4) + tid];

    // Q regs, pre-scaled: lane holds dims [sub*8, sub*8+8) of 4 heads
    const float4* qp = (const float4*)(q + (size_t)(b * HH + kh * G) * HD);
    float4 q00 = qp[0 * 32 + sub * 2], q01 = qp[0 * 32 + sub * 2 + 1];
    float4 q10 = qp[1 * 32 + sub * 2], q11 = qp[1 * 32 + sub * 2 + 1];
    float4 q20 = qp[2 * 32 + sub * 2], q21 = qp[2 * 32 + sub * 2 + 1];
    float4 q30 = qp[3 * 32 + sub * 2], q31 = qp[3 * 32 + sub * 2 + 1];
    #define SCL(v) v.x*=scale; v.y*=scale; v.z*=scale; v.w*=scale;
    SCL(q00) SCL(q01) SCL(q10) SCL(q11) SCL(q20) SCL(q21) SCL(q30) SCL(q31)
    #undef SCL

    __syncthreads();

    // token for pipeline slot j of this half-warp
    const int t0 = cs + w * 2 + half;

    // ================= Pass 1: K -> scores  (depth-4 pipeline, full unroll) =================
    {
        float4 kb0[4], kb1[4];
        bool   kv[NITER];
        #pragma unroll
        for (int j = 0; j < NITER; j++) kv[j] = (t0 + 16 * j) < ce;

        #pragma unroll
        for (int j = 0; j < 3; j++) {         // preload slots 0..2
            if (kv[j]) {
                int t = t0 + 16 * j;
                int bid = sblk[(t - cs) >> 4];
                const float4* kp = (const float4*)(kc + ((size_t)(bid * BS + (t & 15)) * KVH + kh) * HD);
                kb0[j] = kp[sub * 2]; kb1[j] = kp[sub * 2 + 1];
            }
        }

        #pragma unroll
        for (int j = 0; j < NITER; j++) {
            int jl = (j + 3) & 3;             // load slot (3 ahead)
            if (j + 3 < NITER && kv[j + 3]) {
                int t = t0 + 16 * (j + 3);
                int bid = sblk[(t - cs) >> 4];
                const float4* kp = (const float4*)(kc + ((size_t)(bid * BS + (t & 15)) * KVH + kh) * HD);
                kb0[jl] = kp[sub * 2]; kb1[jl] = kp[sub * 2 + 1];
            }
            int jc = j & 3;
            float s0 = dot8(kb0[jc], kb1[jc], q00, q01);
            float s1 = dot8(kb0[jc], kb1[jc], q10, q11);
            float s2 = dot8(kb0[jc], kb1[jc], q20, q21);
            float s3 = dot8(kb0[jc], kb1[jc], q30, q31);
            #pragma unroll
            for (int o = 8; o; o >>= 1) {
                s0 += __shfl_xor_sync(0xffffffffu, s0, o);
                s1 += __shfl_xor_sync(0xffffffffu, s1, o);
                s2 += __shfl_xor_sync(0xffffffffu, s2, o);
                s3 += __shfl_xor_sync(0xffffffffu, s3, o);
            }
            if (kv[j] && sub == 0) {
                int tt = (t0 + 16 * j) - cs;
                sc[0][tt] = s0; sc[1][tt] = s1; sc[2][tt] = s2; sc[3][tt] = s3;
            }
        }
    }
    __syncthreads();

    // ================= chunk softmax (warps 0..3, one head each) =================
    if (w < G) {
        float x0 = sc[w][lane +  0], x1 = sc[w][lane + 32];
        float x2 = sc[w][lane + 64], x3 = sc[w][lane + 96];
        float mx = fmaxf(fmaxf(x0, x1), fmaxf(x2, x3));
        #pragma unroll
        for (int o = 16; o; o >>= 1) mx = fmaxf(mx, __shfl_xor_sync(0xffffffffu, mx, o));
        float p0 = __expf(x0 - mx), p1 = __expf(x1 - mx);
        float p2 = __expf(x2 - mx), p3 = __expf(x3 - mx);
        float ls = p0 + p1 + p2 + p3;
        #pragma unroll
        for (int o = 16; o; o >>= 1) ls += __shfl_xor_sync(0xffffffffu, ls, o);
        sc[w][lane +  0] = p0; sc[w][lane + 32] = p1;
        sc[w][lane + 64] = p2; sc[w][lane + 96] = p3;
        if (lane == 0) g_pml[pml_base + w] = make_float2(mx, ls);
    }
    __syncthreads();

    // ================= Pass 2: V accumulation (depth-3 pipeline, full unroll) =================
    {
        float4 z = make_float4(0, 0, 0, 0);
        float4 a00 = z, a01 = z, a10 = z, a11 = z, a20 = z, a21 = z, a30 = z, a31 = z;

        float4 vb0[3], vb1[3];
        bool   vv[NITER];
        #pragma unroll
        for (int j = 0; j < NITER; j++) vv[j] = (t0 + 16 * j) < ce;

        #pragma unroll
        for (int j = 0; j < 2; j++) {
            if (vv[j]) {
                int t = t0 + 16 * j;
                int bid = sblk[(t - cs) >> 4];
                const float4* vp = (const float4*)(vc + ((size_t)(bid * BS + (t & 15)) * KVH + kh) * HD);
                vb0[j] = vp[sub * 2]; vb1[j] = vp[sub * 2 + 1];
            }
        }

        #pragma unroll
        for (int j = 0; j < NITER; j++) {
            int jl = (j + 2) % 3;
            if (j + 2 < NITER && vv[j + 2]) {
                int t = t0 + 16 * (j + 2);
                int bid = sblk[(t - cs) >> 4];
                const float4* vp = (const float4*)(vc + ((size_t)(bid * BS + (t & 15)) * KVH + kh) * HD);
                vb0[jl] = vp[sub * 2]; vb1[jl] = vp[sub * 2 + 1];
            }
            if (vv[j]) {
                int jc = j % 3;
                float4 c0 = vb0[jc], c1 = vb1[jc];
                int tt = (t0 + 16 * j) - cs;
                float p0 = sc[0][tt], p1 = sc[1][tt], p2 = sc[2][tt], p3 = sc[3][tt];
                a00.x += p0 * c0.x; a00.y += p0 * c0.y; a00.z += p0 * c0.z; a00.w += p0 * c0.w;
                a01.x += p0 * c1.x; a01.y += p0 * c1.y; a01.z += p0 * c1.z; a01.w += p0 * c1.w;
                a10.x += p1 * c0.x; a10.y += p1 * c0.y; a10.z += p1 * c0.z; a10.w += p1 * c0.w;
                a11.x += p1 * c1.x; a11.y += p1 * c1.y; a11.z += p1 * c1.z; a11.w += p1 * c1.w;
                a20.x += p2 * c0.x; a20.y += p2 * c0.y; a20.z += p2 * c0.z; a20.w += p2 * c0.w;
                a21.x += p2 * c1.x; a21.y += p2 * c1.y; a21.z += p2 * c1.z; a21.w += p2 * c1.w;
                a30.x += p3 * c0.x; a30.y += p3 * c0.y; a30.z += p3 * c0.z; a30.w += p3 * c0.w;
                a31.x += p3 * c1.x; a31.y += p3 * c1.y; a31.z += p3 * c1.z; a31.w += p3 * c1.w;
            }
        }

        #define MRG(f) f += __shfl_xor_sync(0xffffffffu, f, 16);
        MRG(a00.x) MRG(a00.y) MRG(a00.z) MRG(a00.w)
        MRG(a01.x) MRG(a01.y) MRG(a01.z) MRG(a01.w)
        MRG(a10.x) MRG(a10.y) MRG(a10.z) MRG(a10.w)
        MRG(a11.x) MRG(a11.y) MRG(a11.z) MRG(a11.w)
        MRG(a20.x) MRG(a20.y) MRG(a20.z) MRG(a20.w)
        MRG(a21.x) MRG(a21.y) MRG(a21.z) MRG(a21.w)
        MRG(a30.x) MRG(a30.y) MRG(a30.z) MRG(a30.w)
        MRG(a31.x) MRG(a31.y) MRG(a31.z) MRG(a31.w)
        #undef MRG

        if (half == 0) {
            float4* p0 = (float4*)&smAcc[w][0][sub * 8]; p0[0] = a00; p0[1] = a01;
            float4* p1 = (float4*)&smAcc[w][1][sub * 8]; p1[0] = a10; p1[1] = a11;
            float4* p2 = (float4*)&smAcc[w][2][sub * 8]; p2[0] = a20; p2[1] = a21;
            float4* p3 = (float4*)&smAcc[w][3][sub * 8]; p3[0] = a30; p3[1] = a31;
        }
    }
    __syncthreads();

    // combine 8 warps; write [b][kh][g][split][d]
    for (int idx = tid; idx < G * HD; idx += 256) {
        int h = idx >> 7;
        int d = idx & 127;
        float O = 0.f;
        #pragma unroll
        for (int ww = 0; ww < NWARP; ww++) O += smAcc[ww][h][d];
        g_pout[((((size_t)(b * KVH + kh) * G + h) * SPLITS) + split) * HD + d] = O;
    }
}

__global__ __launch_bounds__(256)
void attn_reduce_kernel(const int* __restrict__ seqlens, float* __restrict__ out)
{
    const int bh = blockIdx.x;        // b * HH + h_glob
    const int b  = bh >> 5;
    const int hg = bh & 31;
    const int kh = hg >> 2;
    const int g  = hg & 3;
    const int d  = threadIdx.x & 127;
    const int y  = threadIdx.x >> 7;  // split-parity group 0/1

    const int sl = seqlens[b];
    const int ns = (sl + CHUNK - 1) / CHUNK;

    const int mlbase = ((b * KVH + kh) * SPLITS) * G + g;        // + s*G
    const float* pout = g_pout + (((size_t)(b * KVH + kh) * G + g) * SPLITS) * HD;

    __shared__ float shM[2];
    __shared__ float shL[2];
    __shared__ float shO[2][HD];

    // partial max over my parity
    float M = NEG_BIG;
    for (int s = y; s < ns; s += 2) M = fmaxf(M, g_pml[mlbase + s * G].x);
    if (d == 0) shM[y] = M;
    __syncthreads();
    M = fmaxf(shM[0], shM[1]);

    float L = 0.f, O = 0.f;
    #pragma unroll 4
    for (int s = y; s < ns; s += 2) {
        float2 ml = g_pml[mlbase + s * G];
        float e = __expf(ml.x - M);
        L += ml.y * e;
        O += pout[(size_t)s * HD + d] * e;
    }
    shO[y][d] = O;
    if (d == 0) shL[y] = L;
    __syncthreads();
    if (y == 0) {
        float Lt = shL[0] + shL[1];
        out[((size_t)bh) * HD + d] = (shO[0][d] + shO[1][d]) / Lt;
    }
}

extern "C" void kernel_launch(void* const* d_in, const int* in_sizes, int n_in,
                              void* d_out, int out_size) {
    const float* q   = (const float*)d_in[0];
    const float* kc  = (const float*)d_in[1];
    const float* vc  = (const float*)d_in[2];
    const int*   sl  = (const int*)d_in[3];
    const int*   bt  = (const int*)d_in[4];
    float* out = (float*)d_out;

    dim3 g1(SPLITS, KVH, BB);
    attn_split_kernel<<<g1, 256>>>(q, kc, vc, sl, bt);
    attn_reduce_kernel<<<BB * HH, 256>>>(sl, out);
}

// round 5
// speedup vs baseline: 1.4163x; 1.2085x over previous
#include <cuda_runtime.h>
#include <cstdint>

#define BB 32
#define HH 32
#define KVH 8
#define G 4            // HH / KVH
#define HD 128
#define BS 16
#define MAX_KV 4096
#define BPS 256        // blocks per seq
#define CHUNK 256
#define SPLITS (MAX_KV / CHUNK)   // 16
#define NTILE 32       // tokens per staged tile
#define NTK 8          // K tiles per chunk
#define NT 16          // total tiles (K + V)
#define NEG_BIG (-1.0e30f)

// g_pout layout: [b][kh][g][split][d]
__device__ float  g_pout[BB * KVH * G * SPLITS * HD];
__device__ float2 g_pml [BB * KVH * SPLITS * G];

#define CP_ASYNC16(dst_u32, src_ptr) \
    asm volatile("cp.async.cg.shared.global [%0], [%1], 16;\n" \
                 :: "r"(dst_u32), "l"(src_ptr) : "memory")
#define CP_COMMIT()  asm volatile("cp.async.commit_group;" ::: "memory")
#define CP_WAIT(n)   asm volatile("cp.async.wait_group %0;" :: "n"(n) : "memory")

__device__ __forceinline__ float dot8(float4 a0, float4 a1, float4 b0, float4 b1) {
    return a0.x * b0.x + a0.y * b0.y + a0.z * b0.z + a0.w * b0.w +
           a1.x * b1.x + a1.y * b1.y + a1.z * b1.z + a1.w * b1.w;
}

// dynamic smem layout (floats):
//   stage : 3 * NTILE * HD            = 12288
//   sc    : G * CHUNK                 = 1024
//   smAcc : 8 * G * HD                = 4096
#define SMEM_FLOATS (3 * NTILE * HD + G * CHUNK + 8 * G * HD)
#define SMEM_BYTES  (SMEM_FLOATS * 4)

__global__ __launch_bounds__(256, 3)
void attn_split_kernel(const float* __restrict__ q,
                       const float* __restrict__ kc,
                       const float* __restrict__ vc,
                       const int*   __restrict__ seqlens,
                       const int*   __restrict__ btab)
{
    extern __shared__ float dyn[];
    float* stage = dyn;                       // [3][NTILE][HD]
    float* sc    = dyn + 3 * NTILE * HD;      // [G][CHUNK]
    float* smAcc = sc + G * CHUNK;            // [8][G][HD]

    const int split = blockIdx.x;
    const int kh    = blockIdx.y;
    const int b     = blockIdx.z;
    const float scale = 0.08838834764831845f; // 1/sqrt(128)

    const int sl = seqlens[b];
    const int cs = split * CHUNK;
    if (cs >= sl) return;
    const int ce = min(cs + CHUNK, sl);

    const int tid  = threadIdx.x;
    const int w    = tid >> 5;
    const int lane = tid & 31;
    const int half = lane >> 4;
    const int sub  = lane & 15;
    const int hw   = w * 2 + half;            // half-warp id 0..15

    const int pml_base = ((b * KVH + kh) * SPLITS + split) * G;
    const int* tb = btab + b * BPS;

    // ---- tile issue: warp w loads rows w*4..w*4+3; lane supplies 16B ----
    auto issue = [&](int it) {
        const float* basep = (it < NTK) ? kc : vc;
        const int tt0 = (it & (NTK - 1)) * NTILE;          // token offset in chunk
        float* dst_tile = stage + (it % 3) * (NTILE * HD);
        #pragma unroll
        for (int k2 = 0; k2 < 4; k2++) {
            int r = w * 4 + k2;
            int t = cs + tt0 + r;
            if (t < ce) {
                int bid = __ldg(tb + (t >> 4));
                const float* src = basep + ((size_t)(bid * BS + (t & 15)) * KVH + kh) * HD + lane * 4;
                uint32_t daddr = (uint32_t)__cvta_generic_to_shared(dst_tile + r * HD + lane * 4);
                CP_ASYNC16(daddr, src);
            }
        }
        CP_COMMIT();
    };

    // prologue: get tiles 0,1 flying before anything else
    issue(0);
    issue(1);

    // init score buffer (tail slots must stay -inf)
    #pragma unroll
    for (int i = 0; i < 4; i++) sc[tid + 256 * i] = NEG_BIG;

    // Q regs, pre-scaled: lane holds dims [sub*8, sub*8+8) of 4 heads
    const float4* qp = (const float4*)(q + (size_t)(b * HH + kh * G) * HD);
    float4 q00 = qp[0 * 32 + sub * 2], q01 = qp[0 * 32 + sub * 2 + 1];
    float4 q10 = qp[1 * 32 + sub * 2], q11 = qp[1 * 32 + sub * 2 + 1];
    float4 q20 = qp[2 * 32 + sub * 2], q21 = qp[2 * 32 + sub * 2 + 1];
    float4 q30 = qp[3 * 32 + sub * 2], q31 = qp[3 * 32 + sub * 2 + 1];
    #define SCL(v) v.x*=scale; v.y*=scale; v.z*=scale; v.w*=scale;
    SCL(q00) SCL(q01) SCL(q10) SCL(q11) SCL(q20) SCL(q21) SCL(q30) SCL(q31)
    #undef SCL

    // ================= K phase: tiles 0..7 =================
    #pragma unroll
    for (int i = 0; i < NTK; i++) {
        CP_WAIT(1);                     // tile i arrived (for this thread's part)
        __syncthreads();                // all parts arrived; prior compute done
        issue(i + 2);                   // tiles 2..9 (V0,V1 issued at i=6,7)

        const float* buf = stage + (i % 3) * (NTILE * HD);
        #pragma unroll
        for (int h2 = 0; h2 < 2; h2++) {
            int r = hw + 16 * h2;
            int t = cs + i * NTILE + r;
            const float4* rp = (const float4*)(buf + r * HD);
            float4 c0 = rp[sub * 2], c1 = rp[sub * 2 + 1];
            float s0 = dot8(c0, c1, q00, q01);
            float s1 = dot8(c0, c1, q10, q11);
            float s2 = dot8(c0, c1, q20, q21);
            float s3 = dot8(c0, c1, q30, q31);
            #pragma unroll
            for (int o = 8; o; o >>= 1) {
                s0 += __shfl_xor_sync(0xffffffffu, s0, o);
                s1 += __shfl_xor_sync(0xffffffffu, s1, o);
                s2 += __shfl_xor_sync(0xffffffffu, s2, o);
                s3 += __shfl_xor_sync(0xffffffffu, s3, o);
            }
            if (t < ce && sub == 0) {
                int tt = i * NTILE + r;
                sc[0 * CHUNK + tt] = s0; sc[1 * CHUNK + tt] = s1;
                sc[2 * CHUNK + tt] = s2; sc[3 * CHUNK + tt] = s3;
            }
        }
    }
    __syncthreads();   // all scores written

    // ================= chunk softmax: warps 0..3, one head each =================
    if (w < G) {
        float x[8];
        float mx = NEG_BIG;
        #pragma unroll
        for (int j = 0; j < 8; j++) { x[j] = sc[w * CHUNK + lane + 32 * j]; mx = fmaxf(mx, x[j]); }
        #pragma unroll
        for (int o = 16; o; o >>= 1) mx = fmaxf(mx, __shfl_xor_sync(0xffffffffu, mx, o));
        float ls = 0.f;
        #pragma unroll
        for (int j = 0; j < 8; j++) { x[j] = __expf(x[j] - mx); ls += x[j]; }
        #pragma unroll
        for (int o = 16; o; o >>= 1) ls += __shfl_xor_sync(0xffffffffu, ls, o);
        #pragma unroll
        for (int j = 0; j < 8; j++) sc[w * CHUNK + lane + 32 * j] = x[j];
        if (lane == 0) g_pml[pml_base + w] = make_float2(mx, ls);
    }
    // (barrier before V compute happens inside the V loop)

    // ================= V phase: tiles 8..15 =================
    float4 z = make_float4(0, 0, 0, 0);
    float4 a00 = z, a01 = z, a10 = z, a11 = z, a20 = z, a21 = z, a30 = z, a31 = z;

    #define V_COMPUTE(I)                                                        \
    {                                                                           \
        const float* buf = stage + ((I) % 3) * (NTILE * HD);                    \
        const int tt0 = ((I) - NTK) * NTILE;                                    \
        _Pragma("unroll")                                                       \
        for (int h2 = 0; h2 < 2; h2++) {                                        \
            int r = hw + 16 * h2;                                               \
            int t = cs + tt0 + r;                                               \
            if (t < ce) {                                                       \
                const float4* rp = (const float4*)(buf + r * HD);               \
                float4 c0 = rp[sub * 2], c1 = rp[sub * 2 + 1];                  \
                int tt = tt0 + r;                                               \
                float p0 = sc[0 * CHUNK + tt], p1 = sc[1 * CHUNK + tt];         \
                float p2 = sc[2 * CHUNK + tt], p3 = sc[3 * CHUNK + tt];         \
                a00.x += p0 * c0.x; a00.y += p0 * c0.y; a00.z += p0 * c0.z; a00.w += p0 * c0.w; \
                a01.x += p0 * c1.x; a01.y += p0 * c1.y; a01.z += p0 * c1.z; a01.w += p0 * c1.w; \
                a10.x += p1 * c0.x; a10.y += p1 * c0.y; a10.z += p1 * c0.z; a10.w += p1 * c0.w; \
                a11.x += p1 * c1.x; a11.y += p1 * c1.y; a11.z += p1 * c1.z; a11.w += p1 * c1.w; \
                a20.x += p2 * c0.x; a20.y += p2 * c0.y; a20.z += p2 * c0.z; a20.w += p2 * c0.w; \
                a21.x += p2 * c1.x; a21.y += p2 * c1.y; a21.z += p2 * c1.z; a21.w += p2 * c1.w; \
                a30.x += p3 * c0.x; a30.y += p3 * c0.y; a30.z += p3 * c0.z; a30.w += p3 * c0.w; \
                a31.x += p3 * c1.x; a31.y += p3 * c1.y; a31.z += p3 * c1.z; a31.w += p3 * c1.w; \
            }                                                                   \
        }                                                                       \
    }

    #pragma unroll
    for (int i = NTK; i < NT - 1; i++) {
        CP_WAIT(1);
        __syncthreads();
        if (i + 2 < NT) issue(i + 2);
        V_COMPUTE(i);
    }
    CP_WAIT(0);
    __syncthreads();
    V_COMPUTE(NT - 1);
    #undef V_COMPUTE

    // merge the two 16-lane halves (plain sums)
    #define MRG(f) f += __shfl_xor_sync(0xffffffffu, f, 16);
    MRG(a00.x) MRG(a00.y) MRG(a00.z) MRG(a00.w)
    MRG(a01.x) MRG(a01.y) MRG(a01.z) MRG(a01.w)
    MRG(a10.x) MRG(a10.y) MRG(a10.z) MRG(a10.w)
    MRG(a11.x) MRG(a11.y) MRG(a11.z) MRG(a11.w)
    MRG(a20.x) MRG(a20.y) MRG(a20.z) MRG(a20.w)
    MRG(a21.x) MRG(a21.y) MRG(a21.z) MRG(a21.w)
    MRG(a30.x) MRG(a30.y) MRG(a30.z) MRG(a30.w)
    MRG(a31.x) MRG(a31.y) MRG(a31.z) MRG(a31.w)
    #undef MRG

    if (half == 0) {
        float4* p0 = (float4*)&smAcc[(w * G + 0) * HD + sub * 8]; p0[0] = a00; p0[1] = a01;
        float4* p1 = (float4*)&smAcc[(w * G + 1) * HD + sub * 8]; p1[0] = a10; p1[1] = a11;
        float4* p2 = (float4*)&smAcc[(w * G + 2) * HD + sub * 8]; p2[0] = a20; p2[1] = a21;
        float4* p3 = (float4*)&smAcc[(w * G + 3) * HD + sub * 8]; p3[0] = a30; p3[1] = a31;
    }
    __syncthreads();

    // combine 8 warps; write [b][kh][g][split][d]
    #pragma unroll
    for (int idx = tid; idx < G * HD; idx += 256) {
        int h = idx >> 7;
        int d = idx & 127;
        float O = 0.f;
        #pragma unroll
        for (int ww = 0; ww < 8; ww++) O += smAcc[(ww * G + h) * HD + d];
        g_pout[(((size_t)((b * KVH + kh) * G + h)) * SPLITS + split) * HD + d] = O;
    }
}

__global__ __launch_bounds__(256)
void attn_reduce_kernel(const int* __restrict__ seqlens, float* __restrict__ out)
{
    const int bh = blockIdx.x;        // b * HH + h_glob
    const int b  = bh >> 5;
    const int hg = bh & 31;
    const int kh = hg >> 2;
    const int g  = hg & 3;
    const int lane = threadIdx.x & 31;
    const int y    = threadIdx.x >> 5;   // split-group 0..7

    const int sl = seqlens[b];
    const int ns = (sl + CHUNK - 1) / CHUNK;   // 1..16

    const int mlbase = ((b * KVH + kh) * SPLITS) * G + g;        // + s*G
    const float4* pout4 = (const float4*)(g_pout + ((size_t)((b * KVH + kh) * G + g)) * SPLITS * HD);

    __shared__ float  shM[8];
    __shared__ float  shL[8];
    __shared__ float4 shO[8][32];

    float M = NEG_BIG;
    for (int s = y; s < ns; s += 8) M = fmaxf(M, g_pml[mlbase + s * G].x);
    if (lane == 0) shM[y] = M;
    __syncthreads();
    M = shM[0];
    #pragma unroll
    for (int j = 1; j < 8; j++) M = fmaxf(M, shM[j]);

    float L = 0.f;
    float4 O = make_float4(0, 0, 0, 0);
    for (int s = y; s < ns; s += 8) {
        float2 ml = g_pml[mlbase + s * G];
        float e = __expf(ml.x - M);
        L += ml.y * e;
        float4 pv = pout4[s * 32 + lane];
        O.x += e * pv.x; O.y += e * pv.y; O.z += e * pv.z; O.w += e * pv.w;
    }
    shO[y][lane] = O;
    if (lane == 0) shL[y] = L;
    __syncthreads();

    if (y == 0) {
        float Lt = 0.f;
        float4 A = make_float4(0, 0, 0, 0);
        #pragma unroll
        for (int j = 0; j < 8; j++) {
            Lt += shL[j];
            float4 t = shO[j][lane];
            A.x += t.x; A.y += t.y; A.z += t.z; A.w += t.w;
        }
        float inv = 1.0f / Lt;
        A.x *= inv; A.y *= inv; A.z *= inv; A.w *= inv;
        ((float4*)(out + (size_t)bh * HD))[lane] = A;
    }
}

extern "C" void kernel_launch(void* const* d_in, const int* in_sizes, int n_in,
                              void* d_out, int out_size) {
    const float* q   = (const float*)d_in[0];
    const float* kc  = (const float*)d_in[1];
    const float* vc  = (const float*)d_in[2];
    const int*   sl  = (const int*)d_in[3];
    const int*   bt  = (const int*)d_in[4];
    float* out = (float*)d_out;

    cudaFuncSetAttribute(attn_split_kernel,
                         cudaFuncAttributeMaxDynamicSharedMemorySize, SMEM_BYTES);

    dim3 g1(SPLITS, KVH, BB);
    attn_split_kernel<<<g1, 256, SMEM_BYTES>>>(q, kc, vc, sl, bt);
    attn_reduce_kernel<<<BB * HH, 256>>>(sl, out);
}